// round 15
// baseline (speedup 1.0000x reference)
#include <cuda_runtime.h>
#include <cuda_bf16.h>
#include <cstdint>

#define NTOK 16384
#define HDIM 4096
#define NEXP 64
#define TOPK 2

#define BM 128
#define BK 64
#define NCHUNK (HDIM / BK)    // 64
#define THREADS 384           // 8 consumer warps + 4 producer warps

// xh/xl bf16 tiles: 128 rows x 144B stride (128B data), 2 stages each
#define XROW_B 144
#define XTB (BM * XROW_B)               // 18432
#define OFF_XH 0                        // 2 stages -> 36864
#define OFF_XL (2 * XTB)                // 36864 .. 73728
// W bf16 tiles: 64 rows x 144B, 3-slot ring for hi and lo
#define WROW_B 144
#define WTILE_B (NEXP * WROW_B)         // 9216
#define OFF_WH (4 * XTB)                // 73728 .. 101376
#define OFF_WL (OFF_WH + 3 * WTILE_B)   // 101376 .. 129024
#define SMEM_B (OFF_WL + 3 * WTILE_B)   // 129024

__device__ __nv_bfloat16 g_Wh[NEXP * HDIM];
__device__ __nv_bfloat16 g_Wl[NEXP * HDIM];

__device__ __forceinline__ uint32_t smem_u32(const void* p) {
    uint32_t a;
    asm("{ .reg .u64 t; cvta.to.shared.u64 t, %1; cvt.u32.u64 %0, t; }" : "=r"(a) : "l"(p));
    return a;
}

__device__ __forceinline__ void cpa16(uint32_t dst, const void* src) {
    asm volatile("cp.async.cg.shared.global [%0], [%1], 16;" :: "r"(dst), "l"(src) : "memory");
}

__device__ __forceinline__ void ldm4(uint32_t addr, uint32_t* r) {
    asm volatile("ldmatrix.sync.aligned.m8n8.x4.shared.b16 {%0,%1,%2,%3}, [%4];"
                 : "=r"(r[0]), "=r"(r[1]), "=r"(r[2]), "=r"(r[3]) : "r"(addr));
}

__device__ __forceinline__ void sts64(uint32_t addr, uint32_t a, uint32_t b) {
    asm volatile("st.shared.v2.b32 [%0], {%1,%2};" :: "r"(addr), "r"(a), "r"(b) : "memory");
}

// split f32 pair into bf16x2 hi + bf16x2 lo (element0 in lo16)
__device__ __forceinline__ void split_pair(float f0, float f1, uint32_t& hi, uint32_t& lo) {
    asm("cvt.rn.bf16x2.f32 %0, %1, %2;" : "=r"(hi) : "f"(f1), "f"(f0));
    float h0 = __uint_as_float(hi << 16);
    float h1 = __uint_as_float(hi & 0xFFFF0000u);
    float l0 = f0 - h0;
    float l1 = f1 - h1;
    asm("cvt.rn.bf16x2.f32 %0, %1, %2;" : "=r"(lo) : "f"(l1), "f"(l0));
}

__device__ __forceinline__ void mma_bf16(float* d, const uint32_t* a, const uint32_t* b) {
    asm volatile(
        "mma.sync.aligned.m16n8k16.row.col.f32.bf16.bf16.f32 "
        "{%0,%1,%2,%3}, {%4,%5,%6,%7}, {%8,%9}, {%0,%1,%2,%3};"
        : "+f"(d[0]), "+f"(d[1]), "+f"(d[2]), "+f"(d[3])
        : "r"(a[0]), "r"(a[1]), "r"(a[2]), "r"(a[3]), "r"(b[0]), "r"(b[1]));
}

__global__ void wsplit_kernel(const float* __restrict__ W) {
    int i = blockIdx.x * blockDim.x + threadIdx.x;
    float w = W[i];
    __nv_bfloat16 h = __float2bfloat16(w);
    g_Wh[i] = h;
    g_Wl[i] = __float2bfloat16(w - __bfloat162float(h));
}

__global__ __launch_bounds__(THREADS, 1)
void router_mma(const float* __restrict__ x,
                float* __restrict__ out_scores,
                float* __restrict__ out_w,
                float* __restrict__ out_e) {
    extern __shared__ char smem[];
    const uint32_t sbase = smem_u32(smem);
    const int tid = threadIdx.x;
    const int lane = tid & 31;
    const int wid = tid >> 5;        // 0..7 consumers, 8..11 producers
    const int rowBase = blockIdx.x * BM;

    if (wid < 8) {
        // ================= CONSUMER =================
        const int g = lane >> 2;
        const int t = lane & 3;
        const int tokRow0 = wid * 16;

        // W ldmatrix lane offset (expert block of 16)
        const int mtx = lane >> 3;
        const int rr = lane & 7;
        const uint32_t w_lane_off =
            (uint32_t)(((mtx >> 1) * 8 + rr) * WROW_B + (mtx & 1) * 16);
        // A ldmatrix lane offset: row = tokRow0 + (lane&15), colhalf = lane>>4
        const uint32_t a_lane_off =
            (uint32_t)((tokRow0 + (lane & 15)) * XROW_B + (lane >> 4) * 16);

        float accm[8][4] = {};
        float accc[8][4] = {};

        __syncthreads();   // matches producer prologue barrier

        for (int c = 0; c < NCHUNK; c++) {
            const uint32_t xhB = sbase + OFF_XH + (c & 1) * XTB + a_lane_off;
            const uint32_t xlB = sbase + OFF_XL + (c & 1) * XTB + a_lane_off;
            const uint32_t whA = sbase + OFF_WH + (c % 3) * WTILE_B + w_lane_off;
            const uint32_t wlA = sbase + OFF_WL + (c % 3) * WTILE_B + w_lane_off;

#pragma unroll
            for (int ks = 0; ks < 4; ks++) {
                uint32_t ah[4], al[4];
                ldm4(xhB + ks * 32, ah);
                ldm4(xlB + ks * 32, al);

                uint32_t bh[16], bl[16];
#pragma unroll
                for (int e = 0; e < 4; e++)
                    ldm4(whA + e * (16 * WROW_B) + ks * 32, bh + e * 4);
#pragma unroll
                for (int e = 0; e < 4; e++)
                    ldm4(wlA + e * (16 * WROW_B) + ks * 32, bl + e * 4);

#pragma unroll
                for (int nt = 0; nt < 8; nt++)
                    mma_bf16(accm[nt], ah, bh + (nt >> 1) * 4 + (nt & 1) * 2);
#pragma unroll
                for (int nt = 0; nt < 8; nt++)
                    mma_bf16(accc[nt], ah, bl + (nt >> 1) * 4 + (nt & 1) * 2);
#pragma unroll
                for (int nt = 0; nt < 8; nt++)
                    mma_bf16(accc[nt], al, bh + (nt >> 1) * 4 + (nt & 1) * 2);
            }
            __syncthreads();   // stage swap
        }

        // spill logits
        float* lt = (float*)smem;               // [128][65]
#pragma unroll
        for (int nt = 0; nt < 8; nt++) {
            int r0 = tokRow0 + g;
            int cc = nt * 8 + 2 * t;
            lt[r0 * 65 + cc]           = accm[nt][0] + accc[nt][0];
            lt[r0 * 65 + cc + 1]       = accm[nt][1] + accc[nt][1];
            lt[(r0 + 8) * 65 + cc]     = accm[nt][2] + accc[nt][2];
            lt[(r0 + 8) * 65 + cc + 1] = accm[nt][3] + accc[nt][3];
        }
    } else {
        // ================= PRODUCER =================
        const int ptid = tid - 256;          // 0..127
        const int pw = ptid >> 5;            // producer warp 0..3
        const int pl = ptid & 31;
        // coalesced x load: pass p covers rows pw*32 + p*2 + (pl>>4), col float4 (pl&15)
        const int prow = pw * 32 + (pl >> 4);        // + p*2 inside pass loop
        const int pcol4 = pl & 15;

        float4 st[16];

        // ---- prologue: chunk 0 split+store, chunk 1 loaded, W0/W1 issued ----
#pragma unroll
        for (int p = 0; p < 16; p++)
            st[p] = *(const float4*)(x + (size_t)(rowBase + prow + p * 2) * HDIM + pcol4 * 4);
        {
            const uint32_t xh = sbase + OFF_XH;
            const uint32_t xl = sbase + OFF_XL;
#pragma unroll
            for (int p = 0; p < 16; p++) {
                uint32_t h0, l0, h1, l1;
                split_pair(st[p].x, st[p].y, h0, l0);
                split_pair(st[p].z, st[p].w, h1, l1);
                uint32_t off = (uint32_t)((prow + p * 2) * XROW_B + pcol4 * 8);
                sts64(xh + off, h0, h1);
                sts64(xl + off, l0, l1);
            }
        }
#pragma unroll
        for (int p = 0; p < 16; p++)
            st[p] = *(const float4*)(x + (size_t)(rowBase + prow + p * 2) * HDIM + BK + pcol4 * 4);
        // W chunks 0,1 -> slots 0,1
#pragma unroll
        for (int cc = 0; cc < 2; cc++) {
            const uint32_t whD = sbase + OFF_WH + cc * WTILE_B;
            const uint32_t wlD = sbase + OFF_WL + cc * WTILE_B;
#pragma unroll
            for (int j = 0; j < 4; j++) {    // 512 units each of Wh, Wl over 128 threads
                int u = ptid + j * 128;
                int row = u >> 3, q = u & 7;
                cpa16(whD + row * WROW_B + q * 16, g_Wh + (size_t)row * HDIM + cc * BK + q * 8);
                cpa16(wlD + row * WROW_B + q * 16, g_Wl + (size_t)row * HDIM + cc * BK + q * 8);
            }
            asm volatile("cp.async.commit_group;" ::: "memory");
        }
        asm volatile("cp.async.wait_group 0;" ::: "memory");
        __syncthreads();   // stage0/slot0+1 ready; consumers start chunk 0

        for (int c = 0; c < NCHUNK; c++) {
            // split chunk c+1 (in regs) -> stage (c+1)&1
            if (c + 1 < NCHUNK) {
                const uint32_t xh = sbase + OFF_XH + ((c + 1) & 1) * XTB;
                const uint32_t xl = sbase + OFF_XL + ((c + 1) & 1) * XTB;
#pragma unroll
                for (int p = 0; p < 16; p++) {
                    uint32_t h0, l0, h1, l1;
                    split_pair(st[p].x, st[p].y, h0, l0);
                    split_pair(st[p].z, st[p].w, h1, l1);
                    uint32_t off = (uint32_t)((prow + p * 2) * XROW_B + pcol4 * 8);
                    sts64(xh + off, h0, h1);
                    sts64(xl + off, l0, l1);
                }
            }
            // load chunk c+2 f32 -> regs; W chunk c+2 -> slot (c+2)%3
            if (c + 2 < NCHUNK) {
                const int k0 = (c + 2) * BK;
#pragma unroll
                for (int p = 0; p < 16; p++)
                    st[p] = *(const float4*)(x + (size_t)(rowBase + prow + p * 2) * HDIM + k0 + pcol4 * 4);
                const int slot = (c + 2) % 3;
                const uint32_t whD = sbase + OFF_WH + slot * WTILE_B;
                const uint32_t wlD = sbase + OFF_WL + slot * WTILE_B;
#pragma unroll
                for (int j = 0; j < 4; j++) {
                    int u = ptid + j * 128;
                    int row = u >> 3, q = u & 7;
                    cpa16(whD + row * WROW_B + q * 16, g_Wh + (size_t)row * HDIM + k0 + q * 8);
                    cpa16(wlD + row * WROW_B + q * 16, g_Wl + (size_t)row * HDIM + k0 + q * 8);
                }
                asm volatile("cp.async.commit_group;" ::: "memory");
                asm volatile("cp.async.wait_group 1;" ::: "memory");   // W(c+1) landed
            } else {
                asm volatile("cp.async.wait_group 0;" ::: "memory");
            }
            __syncthreads();   // expose stage (c+1)&1 + W slot (c+1)%3
        }
    }

    // ---- epilogue (all 384 threads) ----
    __syncthreads();
    float* lt = (float*)smem;               // [128][65]
    float* rstats = lt + BM * 65;

    if (tid < BM) {
        const float* row = lt + tid * 65;
        float m1 = -1e30f, m2 = -1e30f;
        int i1 = 0, i2 = 0;
#pragma unroll 8
        for (int e = 0; e < NEXP; e++) {
            float v = row[e];
            if (v > m1) { m2 = m1; i2 = i1; m1 = v; i1 = e; }
            else if (v > m2) { m2 = v; i2 = e; }
        }
        float sum = 0.0f;
#pragma unroll 8
        for (int e = 0; e < NEXP; e++) sum += __expf(row[e] - m1);
        rstats[tid] = m1;
        rstats[BM + tid] = 1.0f / sum;

        float e2 = __expf(m2 - m1);
        float dn = 1.0f / (1.0f + e2);
        int gr = rowBase + tid;
        out_w[gr * TOPK + 0] = dn;
        out_w[gr * TOPK + 1] = e2 * dn;
        out_e[gr * TOPK + 0] = (float)i1;
        out_e[gr * TOPK + 1] = (float)i2;
    }
    __syncthreads();

    for (int i = tid; i < BM * NEXP; i += THREADS) {
        int r = i >> 6, cc = i & 63;
        out_scores[(size_t)(rowBase + r) * NEXP + cc] =
            __expf(lt[r * 65 + cc] - rstats[r]) * rstats[BM + r];
    }
}

extern "C" void kernel_launch(void* const* d_in, const int* in_sizes, int n_in,
                              void* d_out, int out_size) {
    const float* x = (const float*)d_in[0];   // [N, H] f32
    const float* W = (const float*)d_in[1];   // [E, H] f32

    float* out_scores = (float*)d_out;                      // N*E
    float* out_w      = out_scores + (size_t)NTOK * NEXP;   // N*TOPK
    float* out_e      = out_w + (size_t)NTOK * TOPK;        // N*TOPK

    cudaFuncSetAttribute(router_mma, cudaFuncAttributeMaxDynamicSharedMemorySize, SMEM_B);

    wsplit_kernel<<<(NEXP * HDIM) / 256, 256>>>(W);
    router_mma<<<NTOK / BM, THREADS, SMEM_B>>>(x, out_scores, out_w, out_e);
}

// round 17
// speedup vs baseline: 1.1294x; 1.1294x over previous
#include <cuda_runtime.h>
#include <cuda_bf16.h>
#include <cuda.h>
#include <cstdint>

#define NTOK 16384
#define HDIM 4096
#define NEXP 64
#define TOPK 2

#define BM 128
#define BK 64
#define NCHUNK (HDIM / BK)    // 64
#define THREADS 256

// smem: [0,32)  full[4] mbarriers; [1024, ...) 4 stages of 49152B:
//   xs0 16KB (k0..k0+31, f32, SW128), xs1 16KB (k0+32..k0+63),
//   wh 8KB (64 experts x 128B bf16, SW128), wl 8KB
#define STG0 1024
#define STAGE_B 49152
#define OFF_XS1 16384
#define OFF_WH 32768
#define OFF_WL 40960
#define SMEM_B (STG0 + 4 * STAGE_B)   // 197632

__device__ __align__(128) __nv_bfloat16 g_Wh[NEXP * HDIM];
__device__ __align__(128) __nv_bfloat16 g_Wl[NEXP * HDIM];

__device__ __forceinline__ uint32_t smem_u32(const void* p) {
    uint32_t a;
    asm("{ .reg .u64 t; cvta.to.shared.u64 t, %1; cvt.u32.u64 %0, t; }" : "=r"(a) : "l"(p));
    return a;
}

__device__ __forceinline__ void ldm4(uint32_t addr, uint32_t* r) {
    asm volatile("ldmatrix.sync.aligned.m8n8.x4.shared.b16 {%0,%1,%2,%3}, [%4];"
                 : "=r"(r[0]), "=r"(r[1]), "=r"(r[2]), "=r"(r[3]) : "r"(addr));
}

__device__ __forceinline__ void split_pair(float f0, float f1, uint32_t& hi, uint32_t& lo) {
    asm("cvt.rn.bf16x2.f32 %0, %1, %2;" : "=r"(hi) : "f"(f1), "f"(f0));
    float h0 = __uint_as_float(hi << 16);
    float h1 = __uint_as_float(hi & 0xFFFF0000u);
    float l0 = f0 - h0;
    float l1 = f1 - h1;
    asm("cvt.rn.bf16x2.f32 %0, %1, %2;" : "=r"(lo) : "f"(l1), "f"(l0));
}

__device__ __forceinline__ void mma_bf16(float* d, const uint32_t* a, const uint32_t* b) {
    asm volatile(
        "mma.sync.aligned.m16n8k16.row.col.f32.bf16.bf16.f32 "
        "{%0,%1,%2,%3}, {%4,%5,%6,%7}, {%8,%9}, {%0,%1,%2,%3};"
        : "+f"(d[0]), "+f"(d[1]), "+f"(d[2]), "+f"(d[3])
        : "r"(a[0]), "r"(a[1]), "r"(a[2]), "r"(a[3]), "r"(b[0]), "r"(b[1]));
}

__device__ __forceinline__ void mbar_init(uint32_t a, uint32_t cnt) {
    asm volatile("mbarrier.init.shared.b64 [%0], %1;" :: "r"(a), "r"(cnt) : "memory");
}

__device__ __forceinline__ void mbar_expect_tx(uint32_t a, uint32_t bytes) {
    asm volatile("mbarrier.arrive.expect_tx.shared.b64 _, [%0], %1;"
                 :: "r"(a), "r"(bytes) : "memory");
}

__device__ __forceinline__ void mbar_wait(uint32_t a, uint32_t parity) {
    asm volatile(
        "{ .reg .pred P;\n\t"
        "WAITLOOP_%=:\n\t"
        "mbarrier.try_wait.parity.acquire.cta.shared::cta.b64 P, [%0], %1, 0x989680;\n\t"
        "@!P bra WAITLOOP_%=;\n\t}"
        :: "r"(a), "r"(parity) : "memory");
}

__device__ __forceinline__ void tma2d(uint32_t dst, const void* map, int cx, int cy,
                                      uint32_t mbar) {
    asm volatile(
        "cp.async.bulk.tensor.2d.shared::cluster.global.tile.mbarrier::complete_tx::bytes "
        "[%0], [%1, {%2, %3}], [%4];"
        :: "r"(dst), "l"(map), "r"(cx), "r"(cy), "r"(mbar) : "memory");
}

__global__ void wsplit_kernel(const float* __restrict__ W) {
    int i = blockIdx.x * blockDim.x + threadIdx.x;
    float w = W[i];
    __nv_bfloat16 h = __float2bfloat16(w);
    g_Wh[i] = h;
    g_Wl[i] = __float2bfloat16(w - __bfloat162float(h));
}

__device__ __forceinline__ void issue_tma(uint32_t sbase, const CUtensorMap* tmx,
                                          const CUtensorMap* tmwh, const CUtensorMap* tmwl,
                                          int rowBase, int c) {
    const int s = c & 3;
    const uint32_t stg = sbase + STG0 + s * STAGE_B;
    const uint32_t mbar = sbase + s * 8;
    const int k0 = c * BK;
    mbar_expect_tx(mbar, STAGE_B);
    tma2d(stg, tmx, k0, rowBase, mbar);
    tma2d(stg + OFF_XS1, tmx, k0 + 32, rowBase, mbar);
    tma2d(stg + OFF_WH, tmwh, k0, 0, mbar);
    tma2d(stg + OFF_WL, tmwl, k0, 0, mbar);
}

__global__ __launch_bounds__(THREADS, 1)
void router_mma(const __grid_constant__ CUtensorMap tmx,
                const __grid_constant__ CUtensorMap tmwh,
                const __grid_constant__ CUtensorMap tmwl,
                float* __restrict__ out_scores,
                float* __restrict__ out_w,
                float* __restrict__ out_e) {
    extern __shared__ char smem[];
    const uint32_t sbase = smem_u32(smem);
    const int tid = threadIdx.x;
    const int lane = tid & 31;
    const int wid = tid >> 5;        // 0..7: warp owns rows wid*16..+15, ALL 64 experts
    const int g = lane >> 2;         // 0..7
    const int t = lane & 3;          // 0..3
    const int rowBase = blockIdx.x * BM;
    const int tokRow0 = wid * 16;

    // W ldmatrix lane geometry (TMA SW128 swizzled tile: 64 rows x 128B)
    const int mtx = lane >> 3;       // matrix 0..3
    const int rr = lane & 7;
    const int h = mtx & 1;
    const uint32_t wrow_off = (uint32_t)(((mtx >> 1) * 8 + rr) * 128);

    if (tid == 0) {
#pragma unroll
        for (int s = 0; s < 4; s++) mbar_init(sbase + s * 8, 1);
    }
    __syncthreads();
    if (tid == 0) {
        issue_tma(sbase, &tmx, &tmwh, &tmwl, rowBase, 0);
        issue_tma(sbase, &tmx, &tmwh, &tmwl, rowBase, 1);
        issue_tma(sbase, &tmx, &tmwh, &tmwl, rowBase, 2);
    }

    float accm[8][4] = {};
    float accc[8][4] = {};

    for (int c = 0; c < NCHUNK; c++) {
        mbar_wait(sbase + (c & 3) * 8, (uint32_t)((c >> 2) & 1));

        const uint32_t stg = sbase + STG0 + (c & 3) * STAGE_B;
        const char* stgp = smem + STG0 + (c & 3) * STAGE_B;

#pragma unroll
        for (int ks = 0; ks < 4; ks++) {
            // ---- W fragments via ldmatrix (SW128 swizzle) ----
            uint32_t wk = ((uint32_t)(2 * ks + h) ^ (uint32_t)rr) * 16;
            uint32_t bh[16], bl[16];
#pragma unroll
            for (int e = 0; e < 4; e++)
                ldm4(stg + OFF_WH + e * 2048 + wrow_off + wk, bh + e * 4);
#pragma unroll
            for (int e = 0; e < 4; e++)
                ldm4(stg + OFF_WL + e * 2048 + wrow_off + wk, bl + e * 4);

            // ---- x fragment: f32 LDS from SW128 tile, split to bf16 hi/lo ----
            uint32_t w0 = (uint32_t)(((ks * 8 + t) & 15) ^ (2 * g));
            uint32_t w4 = (uint32_t)(((ks * 8 + t + 4) & 15) ^ (2 * g));
            const char* xr = stgp + (ks >> 1) * 16384 + (tokRow0 + g) * 128;
            float2 f00 = *(const float2*)(xr + w0 * 8);
            float2 f10 = *(const float2*)(xr + 1024 + w0 * 8);
            float2 f02 = *(const float2*)(xr + w4 * 8);
            float2 f12 = *(const float2*)(xr + 1024 + w4 * 8);
            uint32_t ah[4], al[4];
            split_pair(f00.x, f00.y, ah[0], al[0]);
            split_pair(f10.x, f10.y, ah[1], al[1]);
            split_pair(f02.x, f02.y, ah[2], al[2]);
            split_pair(f12.x, f12.y, ah[3], al[3]);

            // ---- three sweeps of 8 independent HMMAs ----
#pragma unroll
            for (int nt = 0; nt < 8; nt++)
                mma_bf16(accm[nt], ah, bh + (nt >> 1) * 4 + (nt & 1) * 2);
#pragma unroll
            for (int nt = 0; nt < 8; nt++)
                mma_bf16(accc[nt], ah, bl + (nt >> 1) * 4 + (nt & 1) * 2);
#pragma unroll
            for (int nt = 0; nt < 8; nt++)
                mma_bf16(accc[nt], al, bh + (nt >> 1) * 4 + (nt & 1) * 2);
        }

        __syncthreads();   // all warps done with stage (c-1)'s ring slot region
        if (tid == 0 && c + 3 < NCHUNK)
            issue_tma(sbase, &tmx, &tmwh, &tmwl, rowBase, c + 3);
    }

    // ---- epilogue: merge accm+accc, spill logits to smem ----
    __syncthreads();
    float* lt = (float*)smem;               // [128][65]
    float* rstats = lt + BM * 65;
#pragma unroll
    for (int nt = 0; nt < 8; nt++) {
        int r0 = tokRow0 + g;
        int cc = nt * 8 + 2 * t;
        lt[r0 * 65 + cc]           = accm[nt][0] + accc[nt][0];
        lt[r0 * 65 + cc + 1]       = accm[nt][1] + accc[nt][1];
        lt[(r0 + 8) * 65 + cc]     = accm[nt][2] + accc[nt][2];
        lt[(r0 + 8) * 65 + cc + 1] = accm[nt][3] + accc[nt][3];
    }
    __syncthreads();

    if (tid < BM) {
        const float* row = lt + tid * 65;
        float m1 = -1e30f, m2 = -1e30f;
        int i1 = 0, i2 = 0;
#pragma unroll 8
        for (int e = 0; e < NEXP; e++) {
            float v = row[e];
            if (v > m1) { m2 = m1; i2 = i1; m1 = v; i1 = e; }
            else if (v > m2) { m2 = v; i2 = e; }
        }
        float sum = 0.0f;
#pragma unroll 8
        for (int e = 0; e < NEXP; e++) sum += __expf(row[e] - m1);
        rstats[tid] = m1;
        rstats[BM + tid] = 1.0f / sum;

        float e2 = __expf(m2 - m1);
        float dn = 1.0f / (1.0f + e2);
        int gr = rowBase + tid;
        out_w[gr * TOPK + 0] = dn;
        out_w[gr * TOPK + 1] = e2 * dn;
        out_e[gr * TOPK + 0] = (float)i1;
        out_e[gr * TOPK + 1] = (float)i2;
    }
    __syncthreads();

    for (int i = tid; i < BM * NEXP; i += THREADS) {
        int r = i >> 6, cc = i & 63;
        out_scores[(size_t)(rowBase + r) * NEXP + cc] =
            __expf(lt[r * 65 + cc] - rstats[r]) * rstats[BM + r];
    }
}

typedef CUresult (*EncodeFn)(
    CUtensorMap*, CUtensorMapDataType, cuuint32_t, void*,
    const cuuint64_t*, const cuuint64_t*, const cuuint32_t*, const cuuint32_t*,
    CUtensorMapInterleave, CUtensorMapSwizzle, CUtensorMapL2promotion,
    CUtensorMapFloatOOBfill);

extern "C" void kernel_launch(void* const* d_in, const int* in_sizes, int n_in,
                              void* d_out, int out_size) {
    const float* x = (const float*)d_in[0];   // [N, H] f32
    const float* W = (const float*)d_in[1];   // [E, H] f32

    float* out_scores = (float*)d_out;                      // N*E
    float* out_w      = out_scores + (size_t)NTOK * NEXP;   // N*TOPK
    float* out_e      = out_w + (size_t)NTOK * TOPK;        // N*TOPK

    // resolve cuTensorMapEncodeTiled without linking libcuda
    EncodeFn enc = nullptr;
    cudaDriverEntryPointQueryResult qres;
#if CUDART_VERSION >= 12050
    cudaGetDriverEntryPointByVersion("cuTensorMapEncodeTiled", (void**)&enc, 12000,
                                     cudaEnableDefault, &qres);
#else
    cudaGetDriverEntryPoint("cuTensorMapEncodeTiled", (void**)&enc,
                            cudaEnableDefault, &qres);
#endif

    void *whp = nullptr, *wlp = nullptr;
    cudaGetSymbolAddress(&whp, g_Wh);
    cudaGetSymbolAddress(&wlp, g_Wl);

    CUtensorMap tmx{}, tmwh{}, tmwl{};
    {
        cuuint64_t dims[2] = {HDIM, NTOK};
        cuuint64_t strides[1] = {HDIM * sizeof(float)};
        cuuint32_t box[2] = {32, 128};
        cuuint32_t es[2] = {1, 1};
        enc(&tmx, CU_TENSOR_MAP_DATA_TYPE_FLOAT32, 2, (void*)x, dims, strides, box, es,
            CU_TENSOR_MAP_INTERLEAVE_NONE, CU_TENSOR_MAP_SWIZZLE_128B,
            CU_TENSOR_MAP_L2_PROMOTION_L2_128B, CU_TENSOR_MAP_FLOAT_OOB_FILL_NONE);
    }
    {
        cuuint64_t dims[2] = {HDIM, NEXP};
        cuuint64_t strides[1] = {HDIM * sizeof(__nv_bfloat16)};
        cuuint32_t box[2] = {64, 64};
        cuuint32_t es[2] = {1, 1};
        enc(&tmwh, CU_TENSOR_MAP_DATA_TYPE_BFLOAT16, 2, whp, dims, strides, box, es,
            CU_TENSOR_MAP_INTERLEAVE_NONE, CU_TENSOR_MAP_SWIZZLE_128B,
            CU_TENSOR_MAP_L2_PROMOTION_L2_128B, CU_TENSOR_MAP_FLOAT_OOB_FILL_NONE);
        enc(&tmwl, CU_TENSOR_MAP_DATA_TYPE_BFLOAT16, 2, wlp, dims, strides, box, es,
            CU_TENSOR_MAP_INTERLEAVE_NONE, CU_TENSOR_MAP_SWIZZLE_128B,
            CU_TENSOR_MAP_L2_PROMOTION_L2_128B, CU_TENSOR_MAP_FLOAT_OOB_FILL_NONE);
    }

    cudaFuncSetAttribute(router_mma, cudaFuncAttributeMaxDynamicSharedMemorySize, SMEM_B);

    wsplit_kernel<<<(NEXP * HDIM) / 256, 256>>>(W);
    router_mma<<<NTOK / BM, THREADS, SMEM_B>>>(tmx, tmwh, tmwl,
                                               out_scores, out_w, out_e);
}